// round 9
// baseline (speedup 1.0000x reference)
#include <cuda_runtime.h>
#include <cuda_bf16.h>
#include <cstdint>

#define EDGES 300000
#define HDIM 128
#define L1_ROWS 1528000   // sum of n_dst over the 22 layer-1 relations

#if defined(__CUDA_ARCH_FEAT_SM103_ALL) || defined(__CUDA_ARCH_FEAT_SM101_ALL) || defined(__CUDA_ARCH_FEAT_SM100_ALL)
#define USE_TC 1
#else
#define USE_TC 0
#endif

// ---------------- static graph metadata -------------------------------------
static const int NODE_N[10] = {50000,2000,80000,10000,2000,150000,120000,100000,60000,40000};
struct RelDef { int s, d, ei, flip; };
static const RelDef REL[26] = {
  {0,1,0,0},{1,0,0,1},{0,2,1,0},{2,0,1,1},{0,3,2,0},{3,0,2,1},
  {0,4,3,0},{4,0,3,1},{0,5,4,0},{5,0,4,1},{0,6,5,0},{6,0,5,1},
  {6,7,6,0},{7,6,6,1},{5,6,7,0},{6,5,7,1},{5,7,8,0},{7,5,8,1},
  {4,5,9,0},{5,4,9,1},{4,3,10,0},{3,4,10,1},{2,8,11,0},{8,2,11,1},
  {2,9,12,0},{9,2,12,1}};
static const int L1_RELS[22] = {0,1,2,3,4,5,6,7,8,9,10,11,13,14,15,17,18,19,20,21,23,25};
static const int L2_RELS[6] = {1,3,5,7,9,11};

// ---------------- device scratch ---------------------------------------------
__device__ __align__(256) float g_ZBUF[(size_t)L1_ROWS * HDIM + L1_ROWS];
#define AGG_PTR   (g_ZBUF)
#define DEG_PTR   (g_ZBUF + (size_t)L1_ROWS * HDIM)
__device__ __align__(256) float g_XBUF[(size_t)414000 * HDIM];
__device__ __align__(256) float g_CRS[(size_t)50000 * HDIM];
__device__ float g_BSUM[8 * 128];
__device__ __align__(256) float g_WSUM[8 * 16384];   // fallback-only (dead on sm_103a)
__device__ __align__(256) __nv_bfloat16 g_Bimg[36 * 32768];

// ---------------- param structs ------------------------------------------------
struct ScatParams {
  const int*   ei[22];
  const float* xsrc[22];
  long long    aggOff[22];
  int          flip[22];
};
struct GemmParams {
  int nJobs, relu;
  int rowBlkStart[8];
  int nRows[7];
  const float* xCur[7];
  float*       outPtr[7];
  int          bsumIdx[7];
  int          nRel[7];
  int          bimg[7][7];
  const float* wlRaw[7][6];
  long long    aggOff[7][6];
  long long    degOff[7][6];
};
struct BPrepParams {
  const float* src[36][6];
  int nSrc[36];
  const float* bsrc[8][6];
  int bN[8];
};

// ---------------- PTX helpers (arch-guarded) -----------------------------------
#if USE_TC
__device__ __forceinline__ uint32_t smem_u32(const void* p) {
  uint32_t a;
  asm("{ .reg .u64 t; cvta.to.shared.u64 t, %1; cvt.u32.u64 %0, t; }" : "=r"(a) : "l"(p));
  return a;
}
__device__ __forceinline__ int elect_one() {
  uint32_t p;
  asm volatile("{ .reg .pred P; elect.sync _|P, 0xFFFFFFFF; selp.b32 %0, 1, 0, P; }" : "=r"(p));
  return (int)p;
}
__device__ __forceinline__ uint64_t make_desc(uint32_t addr) {
  return 0x4000404000010000ULL | (uint64_t)((addr >> 4) & 0x3FFF);
}
__device__ __forceinline__ void mma_f16_ts(uint32_t d, uint32_t a_tmem, uint64_t b,
                                           uint32_t idesc, uint32_t en) {
  asm volatile(
    "{\n\t.reg .pred p;\n\t"
    "setp.ne.u32 p, %4, 0;\n\t"
    "tcgen05.mma.cta_group::1.kind::f16 [%0], [%1], %2, %3, {%5, %5, %5, %5}, p;\n\t}"
    :: "r"(d), "r"(a_tmem), "l"(b), "r"(idesc), "r"(en), "r"(0u) : "memory");
}
__device__ __forceinline__ void mbar_init(uint32_t mbar, uint32_t cnt) {
  asm volatile("mbarrier.init.shared.b64 [%0], %1;" :: "r"(mbar), "r"(cnt) : "memory");
}
__device__ __forceinline__ void mbar_inval(uint32_t mbar) {
  asm volatile("mbarrier.inval.shared.b64 [%0];" :: "r"(mbar) : "memory");
}
__device__ __forceinline__ void mbar_wait(uint32_t mbar, uint32_t parity) {
  asm volatile(
    "{\n\t.reg .pred P;\n\t"
    "WL_%=:\n\t"
    "mbarrier.try_wait.parity.acquire.cta.shared::cta.b64 P, [%0], %1, 0x989680;\n\t"
    "@P bra WD_%=;\n\t"
    "bra WL_%=;\n\t"
    "WD_%=:\n\t}\n"
    :: "r"(mbar), "r"(parity) : "memory");
}
__device__ __forceinline__ void tc_commit(uint32_t mbar) {
  asm volatile(
    "tcgen05.commit.cta_group::1.mbarrier::arrive::one.shared::cluster.b64 [%0];"
    :: "r"(mbar) : "memory");
}
// 64KB bulk copy global->smem, completion on mbar (expect_tx + UBLKCP)
__device__ __forceinline__ void bulkB(uint32_t dst, const void* src, uint32_t mbar) {
  asm volatile("mbarrier.arrive.expect_tx.shared.b64 _, [%0], %1;"
               :: "r"(mbar), "r"(65536u) : "memory");
  asm volatile(
    "{\n\t.reg .u64 gs;\n\t"
    "cvta.to.global.u64 gs, %1;\n\t"
    "cp.async.bulk.shared::cta.global.mbarrier::complete_tx::bytes [%0], [gs], %2, [%3];\n\t}"
    :: "r"(dst), "l"(src), "r"(65536u), "r"(mbar) : "memory");
}
#define TC_ALLOC(sm, n)   asm volatile("tcgen05.alloc.cta_group::1.sync.aligned.shared::cta.b32 [%0], %1;" :: "r"(sm), "r"(n) : "memory")
#define TC_DEALLOC(t, n)  asm volatile("tcgen05.dealloc.cta_group::1.sync.aligned.b32 %0, %1;" :: "r"(t), "r"(n))
#define TC_RELINQ()       asm volatile("tcgen05.relinquish_alloc_permit.cta_group::1.sync.aligned;")
#define TC_FENCE_AFTER()  asm volatile("tcgen05.fence::after_thread_sync;" ::: "memory")
#define TC_FENCE_BEFORE() asm volatile("tcgen05.fence::before_thread_sync;" ::: "memory")
#define TC_WAIT_LD()      asm volatile("tcgen05.wait::ld.sync.aligned;" ::: "memory")
#define TC_WAIT_ST()      asm volatile("tcgen05.wait::st.sync.aligned;" ::: "memory")

#define TCGEN05_ST_32X32B_X8(tmem_addr, r) \
  asm volatile( \
    "tcgen05.st.sync.aligned.32x32b.x8.b32 [%0], " \
    "{%1, %2, %3, %4, %5, %6, %7, %8};" \
    :: "r"(tmem_addr), \
       "r"((r)[0]), "r"((r)[1]), "r"((r)[2]), "r"((r)[3]), \
       "r"((r)[4]), "r"((r)[5]), "r"((r)[6]), "r"((r)[7]) \
    : "memory")

#define LDTM_X32(r, addr) \
  asm volatile( \
    "tcgen05.ld.sync.aligned.32x32b.x32.b32 " \
    "{%0, %1, %2, %3, %4, %5, %6, %7, " \
    " %8, %9, %10, %11, %12, %13, %14, %15, " \
    " %16, %17, %18, %19, %20, %21, %22, %23, " \
    " %24, %25, %26, %27, %28, %29, %30, %31}, [%32];" \
    : "=r"((r)[0]),  "=r"((r)[1]),  "=r"((r)[2]),  "=r"((r)[3]), \
      "=r"((r)[4]),  "=r"((r)[5]),  "=r"((r)[6]),  "=r"((r)[7]), \
      "=r"((r)[8]),  "=r"((r)[9]),  "=r"((r)[10]), "=r"((r)[11]), \
      "=r"((r)[12]), "=r"((r)[13]), "=r"((r)[14]), "=r"((r)[15]), \
      "=r"((r)[16]), "=r"((r)[17]), "=r"((r)[18]), "=r"((r)[19]), \
      "=r"((r)[20]), "=r"((r)[21]), "=r"((r)[22]), "=r"((r)[23]), \
      "=r"((r)[24]), "=r"((r)[25]), "=r"((r)[26]), "=r"((r)[27]), \
      "=r"((r)[28]), "=r"((r)[29]), "=r"((r)[30]), "=r"((r)[31]) \
    : "r"(addr))

#define MMA_IDESC 0x8200490u

// TMEM columns (512): D0 @0, D1 @128, A buf b: hi @256+b*128, lo @256+b*128+64
#define TM_D(d)    ((uint32_t)(d) * 128u)
#define TM_AHI(b)  (256u + (uint32_t)(b) * 128u)
#define TM_ALO(b)  (256u + (uint32_t)(b) * 128u + 64u)

__device__ __forceinline__ uint32_t pack_hi(float a, float b, float& ra, float& rb) {
  __nv_bfloat16 ha = __float2bfloat16(a), hb = __float2bfloat16(b);
  ra = a - __bfloat162float(ha); rb = b - __bfloat162float(hb);
  return (uint32_t)__bfloat16_as_ushort(ha) | ((uint32_t)__bfloat16_as_ushort(hb) << 16);
}
__device__ __forceinline__ uint32_t pack_bf(float a, float b) {
  __nv_bfloat16 ha = __float2bfloat16(a), hb = __float2bfloat16(b);
  return (uint32_t)__bfloat16_as_ushort(ha) | ((uint32_t)__bfloat16_as_ushort(hb) << 16);
}
#endif  // USE_TC

// smem layout: 3 B buffers (triple-buffered bulk copies), A lives in regs/TMEM
#define SM_TMEM   0
#define SM_MBAR0  8
#define SM_MBAR1  16
#define SM_BBAR0  24
#define SM_BBAR1  32
#define SM_BBAR2  40
#define SM_B(m)   (1024 + (m) * 65536)
#define SM_BYTES  (1024 + 3 * 65536)   // 197632

// ---------------- simple kernels ------------------------------------------------
__global__ void deg_kernel(ScatParams S) {
  int rel = blockIdx.y;
  int e = blockIdx.x * blockDim.x + threadIdx.x;
  if (e >= EDGES) return;
  const int* ei = S.ei[rel];
  int dstRow = S.flip[rel] ? 0 : EDGES;
  int dst = __ldg(ei + dstRow + e);
  atomicAdd(DEG_PTR + S.aggOff[rel] + dst, 1.0f);
}

__global__ void scatter_kernel(ScatParams S) {
  int rel  = blockIdx.y;
  int lane = threadIdx.x & 31;
  int warp = threadIdx.x >> 5;
  const int* ei   = S.ei[rel];
  const float* xs = S.xsrc[rel];
  float* aggBase  = AGG_PTR + (size_t)S.aggOff[rel] * HDIM;
  int srcRow = S.flip[rel] ? EDGES : 0;
  int dstRow = EDGES - srcRow;
  int e0 = blockIdx.x * 8 + warp;
#pragma unroll
  for (int i = 0; i < 4; ++i) {
    int e   = e0 + i * 75000;
    int src = __ldg(ei + srcRow + e);
    int dst = __ldg(ei + dstRow + e);
    float4 v = __ldg(reinterpret_cast<const float4*>(xs + (size_t)src * HDIM) + lane);
    float* p = aggBase + (size_t)dst * HDIM + lane * 4;
    asm volatile("red.global.add.v4.f32 [%0], {%1,%2,%3,%4};"
                 :: "l"(p), "f"(v.x), "f"(v.y), "f"(v.z), "f"(v.w) : "memory");
  }
}

// ---------------- weight image prep (sum + f32 -> swizzled bf16 hi/lo) --------
__global__ void bprep_kernel(BPrepParams P) {
  if (blockIdx.x == 36) {
    if (blockIdx.y == 0 && threadIdx.x < 128) {
      for (int j = 0; j < 8; ++j) {
        float s = 0.f;
        for (int q = 0; q < P.bN[j]; ++q) s += __ldg(P.bsrc[j][q] + threadIdx.x);
        g_BSUM[j * 128 + threadIdx.x] = s;
      }
    }
    return;
  }
  int img = blockIdx.x;
  int n = P.nSrc[img];
  char* dst = (char*)g_Bimg + (size_t)img * 65536;
  int lo = blockIdx.y * 4096;
  int hi = lo + 4096;
  for (int idx = lo + threadIdx.x; idx < hi; idx += blockDim.x) {
    int k = idx >> 7, nn = idx & 127;
    float v = 0.f;
    for (int q = 0; q < n; ++q) v += __ldg(P.src[img][q] + idx);
    __nv_bfloat16 h = __float2bfloat16(v);
    __nv_bfloat16 l = __float2bfloat16(v - __bfloat162float(h));
    uint32_t atom = (uint32_t)(nn >> 3) + (uint32_t)(k >> 6) * 16u;
    uint32_t off  = atom * 1024u + (uint32_t)(nn & 7) * 128u + (uint32_t)(k & 63) * 2u;
    uint32_t sw   = off ^ ((off >> 3) & 0x70);
    *(unsigned short*)(dst + sw)         = __bfloat16_as_ushort(h);
    *(unsigned short*)(dst + 32768 + sw) = __bfloat16_as_ushort(l);
  }
}

// ---------------- persistent fused GEMM (TS, bulk-B, register-pipelined A) ------
// grid=148, 512 threads. A: warps 0-7, v[16] register preload across chunks,
// STTM into double-buffered TMEM. B: one thread issues cp.async.bulk into
// triple-buffered smem one chunk ahead. Epilogue: warps 12-15, overlapped.
__global__ __launch_bounds__(512, 1) void gemm_kernel(GemmParams P) {
  extern __shared__ char smem[];
  int tid = threadIdx.x;
  int nTiles = P.rowBlkStart[P.nJobs];

#if USE_TC
  uint32_t sbase = smem_u32(smem);
  int wid = tid >> 5;

  if (wid == 0) { TC_ALLOC(sbase + SM_TMEM, 512); TC_RELINQ(); }
  if (tid == 0) {
    mbar_init(sbase + SM_MBAR0, 1); mbar_init(sbase + SM_MBAR1, 1);
    mbar_init(sbase + SM_BBAR0, 1); mbar_init(sbase + SM_BBAR1, 1);
    mbar_init(sbase + SM_BBAR2, 1);
  }
  __syncthreads();
  uint32_t tmem;
  asm volatile("ld.shared.b32 %0, [%1];" : "=r"(tmem) : "r"(sbase + SM_TMEM));

  uint32_t woff = ((uint32_t)(tid >> 5) & 3u) << 21;
  uint64_t db_hi[3] = { make_desc(sbase + SM_B(0)), make_desc(sbase + SM_B(1)),
                        make_desc(sbase + SM_B(2)) };
  uint64_t db_lo[3] = { make_desc(sbase + SM_B(0) + 32768), make_desc(sbase + SM_B(1) + 32768),
                        make_desc(sbase + SM_B(2) + 32768) };
  uint32_t bbar[3] = { sbase + SM_BBAR0, sbase + SM_BBAR1, sbase + SM_BBAR2 };

  // tile state
  int tile = blockIdx.x;
  bool valid = tile < nTiles;
  int j = 0, row0 = 0, nrows = 0, nCh = 0, c = 0;
  if (valid) {
#pragma unroll
    for (int q = 1; q < 7; ++q)
      if (q < P.nJobs && tile >= P.rowBlkStart[q]) j = q;
    row0 = (tile - P.rowBlkStart[j]) * 128;
    nrows = P.nRows[j];
    nCh = P.nRel[j] + 1;
  }

  // A-warp persistent registers
  float4 v[16];
  float sc = 1.0f;
  int ar = tid & 127, half = tid >> 7;   // meaningful for tid<256

  auto loadA = [&](int jj, int rr0, int nn, int cc) {
    int gr = rr0 + ar;
    bool av = gr < nn;
    const float* Ab;
    const float* deg = nullptr;
    if (cc == 0) Ab = P.xCur[jj];
    else { Ab = AGG_PTR + (size_t)P.aggOff[jj][cc - 1] * HDIM; deg = DEG_PTR + P.degOff[jj][cc - 1]; }
    sc = 1.0f;
    if (deg && av) sc = 1.0f / fmaxf(__ldg(deg + gr), 1.0f);
    const float4* asrc = reinterpret_cast<const float4*>(Ab + (size_t)gr * HDIM + half * 64);
#pragma unroll
    for (int i = 0; i < 16; ++i) {
      v[i] = make_float4(0.f, 0.f, 0.f, 0.f);
      if (av) v[i] = __ldg(asrc + i);
    }
  };

  auto storeA = [&](int b) {
#pragma unroll
    for (int r4 = 0; r4 < 4; ++r4) {
      uint32_t hv[8], lv[8];
#pragma unroll
      for (int i = 0; i < 4; ++i) {
        float4 t = v[r4 * 4 + i];
        float ax = t.x * sc, ay = t.y * sc, az = t.z * sc, aw = t.w * sc;
        float rx, ry, rz, rw;
        hv[2 * i]     = pack_hi(ax, ay, rx, ry);
        hv[2 * i + 1] = pack_hi(az, aw, rz, rw);
        lv[2 * i]     = pack_bf(rx, ry);
        lv[2 * i + 1] = pack_bf(rz, rw);
      }
      uint32_t coff = (uint32_t)(half * 32 + r4 * 8);
      TCGEN05_ST_32X32B_X8(tmem + TM_AHI(b) + coff + woff, hv);
      TCGEN05_ST_32X32B_X8(tmem + TM_ALO(b) + coff + woff, lv);
    }
    TC_WAIT_ST();
    TC_FENCE_BEFORE();
  };

  auto dispatch = [&](int cc, int b, int dpar, int m) {
    TC_FENCE_AFTER();
    uint32_t en = (cc > 0) ? 1u : 0u;
    uint32_t dst = tmem + TM_D(dpar);
#pragma unroll
    for (int ks = 0; ks < 8; ++ks) {
      uint64_t boff = (ks < 4) ? (uint64_t)(ks * 2) : (uint64_t)(1024 + (ks - 4) * 2);
      uint32_t ahi = tmem + TM_AHI(b) + (uint32_t)ks * 8u;
      uint32_t alo = tmem + TM_ALO(b) + (uint32_t)ks * 8u;
      mma_f16_ts(dst, ahi, db_hi[m] + boff, MMA_IDESC, en); en = 1u;
      mma_f16_ts(dst, ahi, db_lo[m] + boff, MMA_IDESC, 1u);
      mma_f16_ts(dst, alo, db_hi[m] + boff, MMA_IDESC, 1u);
    }
    tc_commit(sbase + (b ? SM_MBAR1 : SM_MBAR0));
  };

  auto epilogue = [&](int pj, int prow0, int pnrows, int pd) {
    TC_FENCE_AFTER();
    int lid = tid & 31;
    int sub = wid & 3;
    int gr = prow0 + sub * 32 + lid;
    const float* bs = g_BSUM + P.bsumIdx[pj] * 128;
    float* op = P.outPtr[pj] + (size_t)gr * HDIM;
#pragma unroll
    for (int nb = 0; nb < 4; ++nb) {
      uint32_t dr[32];
      LDTM_X32(dr, tmem + TM_D(pd) + nb * 32);
      TC_WAIT_LD();
      if (gr < pnrows) {
#pragma unroll
        for (int q = 0; q < 32; q += 4) {
          float4 o;
          o.x = __uint_as_float(dr[q + 0]) + __ldg(bs + nb * 32 + q + 0);
          o.y = __uint_as_float(dr[q + 1]) + __ldg(bs + nb * 32 + q + 1);
          o.z = __uint_as_float(dr[q + 2]) + __ldg(bs + nb * 32 + q + 2);
          o.w = __uint_as_float(dr[q + 3]) + __ldg(bs + nb * 32 + q + 3);
          if (P.relu) {
            o.x = fmaxf(o.x, 0.f); o.y = fmaxf(o.y, 0.f);
            o.z = fmaxf(o.z, 0.f); o.w = fmaxf(o.w, 0.f);
          }
          *reinterpret_cast<float4*>(op + nb * 32 + q) = o;
        }
      }
    }
    TC_FENCE_BEFORE();
  };

  // prologue: preload A(0) into registers, issue bulk B(0)
  if (valid) {
    if (tid < 256) loadA(j, row0, nrows, 0);
    if (tid == 256)
      bulkB(sbase + SM_B(0), (const char*)g_Bimg + (size_t)P.bimg[j][0] * 65536, bbar[0]);
  }

  int g = 0, m = 0;
  uint32_t ph[2] = {0u, 0u};
  uint32_t bp[3] = {0u, 0u, 0u};
  int prevJ = -1, prevRow0 = 0, prevNrows = 0, prevD = 0;
  int tcount = 0;

  while (valid) {
    // lookahead: next chunk (possibly next tile)
    int nc = c + 1, ntile = tile;
    int nj = j, nrow0 = row0, nn = nrows;
    bool nvalid = true;
    if (nc == nCh) {
      nc = 0; ntile = tile + gridDim.x;
      nvalid = ntile < nTiles;
      if (nvalid) {
        nj = 0;
#pragma unroll
        for (int q = 1; q < 7; ++q)
          if (q < P.nJobs && ntile >= P.rowBlkStart[q]) nj = q;
        nrow0 = (ntile - P.rowBlkStart[nj]) * 128;
        nn = P.nRows[nj];
      }
    }
    int mn = (m == 2) ? 0 : m + 1;
    int b = g & 1;
    int dpar = tcount & 1;

    if (g >= 2) { mbar_wait(sbase + (b ? SM_MBAR1 : SM_MBAR0), ph[b]); ph[b] ^= 1; }

    if (tid < 256) {
      storeA(b);
      if (nvalid) loadA(nj, nrow0, nn, nc);      // prefetch next chunk's A
    } else if (tid == 256) {
      if (nvalid)
        bulkB(sbase + SM_B(mn), (const char*)g_Bimg + (size_t)P.bimg[nj][nc] * 65536, bbar[mn]);
    } else if (wid >= 12) {
      if (c == 1 && prevJ >= 0) epilogue(prevJ, prevRow0, prevNrows, prevD);
    }
    __syncthreads();
    if (wid == 0 && elect_one()) {
      mbar_wait(bbar[m], bp[m]);                 // B(g) bulk landed
      dispatch(c, b, dpar, m);
    }
    bp[m] ^= 1;   // all threads track B phases uniformly

    // advance
    if (c == nCh - 1) {
      prevJ = j; prevRow0 = row0; prevNrows = nrows; prevD = dpar; ++tcount;
    }
    c = nc;
    if (ntile != tile) {
      tile = ntile; j = nj; row0 = nrow0; nrows = nn;
      if (nvalid) nCh = P.nRel[nj] + 1;
    }
    valid = nvalid; ++g; m = mn;
  }

  // drain last two commits, then final epilogue
  if (g >= 2) {
    int b = (g - 2) & 1;
    mbar_wait(sbase + (b ? SM_MBAR1 : SM_MBAR0), ph[b]); ph[b] ^= 1;
  }
  if (g >= 1) {
    int b = (g - 1) & 1;
    mbar_wait(sbase + (b ? SM_MBAR1 : SM_MBAR0), ph[b]); ph[b] ^= 1;
  }
  if (wid >= 12 && prevJ >= 0) epilogue(prevJ, prevRow0, prevNrows, prevD);

  __syncthreads();
  if (tid == 0) {
    mbar_inval(sbase + SM_MBAR0); mbar_inval(sbase + SM_MBAR1);
    mbar_inval(sbase + SM_BBAR0); mbar_inval(sbase + SM_BBAR1);
    mbar_inval(sbase + SM_BBAR2);
  }
  __syncthreads();
  if (wid == 0) TC_DEALLOC(tmem, 512);

#else  // ---------------- FFMA fallback (non-"a" pass; never executes) ----------
  float (*As)[128] = reinterpret_cast<float (*)[128]>(smem);
  float (*Bs)[128] = reinterpret_cast<float (*)[128]>(smem + 16 * 128 * 4);
  bool act = tid < 256;

  for (int tile = blockIdx.x; tile < nTiles; tile += gridDim.x) {
    int j = 0;
#pragma unroll
    for (int q = 1; q < 7; ++q)
      if (q < P.nJobs && tile >= P.rowBlkStart[q]) j = q;
    int row0  = (tile - P.rowBlkStart[j]) * 128;
    int nrows = P.nRows[j];

    int tx = tid & 15, ty = (tid >> 4) & 15;
    int arow = (tid & 255) >> 2;
    int acol = (tid & 3) << 2;
    int brow = (tid & 255) >> 5;
    int bcol = (tid & 31) << 2;

    float acc[8][8];
#pragma unroll
    for (int i = 0; i < 8; ++i)
#pragma unroll
      for (int q = 0; q < 8; ++q) acc[i][q] = 0.f;

    int nChunks = P.nRel[j] + 1;
    for (int c = 0; c < nChunks; ++c) {
      const float* Ab;
      const float* Bb;
      const float* deg = nullptr;
      if (c == 0) {
        Ab = P.xCur[j];
        Bb = g_WSUM + (size_t)P.bsumIdx[j] * 16384;
      } else {
        Ab  = AGG_PTR + (size_t)P.aggOff[j][c - 1] * HDIM;
        Bb  = P.wlRaw[j][c - 1];
        deg = DEG_PTR + P.degOff[j][c - 1];
      }
      for (int kt = 0; kt < 8; ++kt) {
        if (act) {
#pragma unroll
          for (int h = 0; h < 2; ++h) {
            int r = row0 + arow + h * 64;
            float4 vv = make_float4(0.f, 0.f, 0.f, 0.f);
            if (r < nrows) {
              vv = *reinterpret_cast<const float4*>(Ab + (size_t)r * HDIM + kt * 16 + acol);
              if (deg) {
                float s = 1.0f / fmaxf(__ldg(deg + r), 1.0f);
                vv.x *= s; vv.y *= s; vv.z *= s; vv.w *= s;
              }
            }
            As[acol + 0][arow + h * 64] = vv.x;
            As[acol + 1][arow + h * 64] = vv.y;
            As[acol + 2][arow + h * 64] = vv.z;
            As[acol + 3][arow + h * 64] = vv.w;
          }
#pragma unroll
          for (int h = 0; h < 2; ++h) {
            int kr = kt * 16 + brow + h * 8;
            *reinterpret_cast<float4*>(&Bs[brow + h * 8][bcol]) =
                *reinterpret_cast<const float4*>(Bb + (size_t)kr * HDIM + bcol);
          }
        }
        __syncthreads();
        if (act) {
#pragma unroll
          for (int k = 0; k < 16; ++k) {
            float a[8], b[8];
            *reinterpret_cast<float4*>(&a[0]) = *reinterpret_cast<const float4*>(&As[k][ty * 4]);
            *reinterpret_cast<float4*>(&a[4]) = *reinterpret_cast<const float4*>(&As[k][ty * 4 + 64]);
            *reinterpret_cast<float4*>(&b[0]) = *reinterpret_cast<const float4*>(&Bs[k][tx * 4]);
            *reinterpret_cast<float4*>(&b[4]) = *reinterpret_cast<const float4*>(&Bs[k][tx * 4 + 64]);
#pragma unroll
            for (int i = 0; i < 8; ++i)
#pragma unroll
              for (int q = 0; q < 8; ++q) acc[i][q] += a[i] * b[q];
          }
        }
        __syncthreads();
      }
    }

    if (act) {
      const float* bs = g_BSUM + P.bsumIdx[j] * 128;
      float bc[8];
#pragma unroll
      for (int q = 0; q < 4; ++q) { bc[q] = bs[tx * 4 + q]; bc[q + 4] = bs[tx * 4 + 64 + q]; }
      float* outp = P.outPtr[j];
#pragma unroll
      for (int i = 0; i < 8; ++i) {
        int rr = ty * 4 + ((i < 4) ? i : (64 + i - 4));
        int r = row0 + rr;
        if (r >= nrows) continue;
        float4 o0, o1;
        o0.x = acc[i][0] + bc[0]; o0.y = acc[i][1] + bc[1];
        o0.z = acc[i][2] + bc[2]; o0.w = acc[i][3] + bc[3];
        o1.x = acc[i][4] + bc[4]; o1.y = acc[i][5] + bc[5];
        o1.z = acc[i][6] + bc[6]; o1.w = acc[i][7] + bc[7];
        if (P.relu) {
          o0.x = fmaxf(o0.x, 0.f); o0.y = fmaxf(o0.y, 0.f); o0.z = fmaxf(o0.z, 0.f); o0.w = fmaxf(o0.w, 0.f);
          o1.x = fmaxf(o1.x, 0.f); o1.y = fmaxf(o1.y, 0.f); o1.z = fmaxf(o1.z, 0.f); o1.w = fmaxf(o1.w, 0.f);
        }
        *reinterpret_cast<float4*>(outp + (size_t)r * HDIM + tx * 4)      = o0;
        *reinterpret_cast<float4*>(outp + (size_t)r * HDIM + tx * 4 + 64) = o1;
      }
    }
    __syncthreads();
  }
#endif
}

// final: out[50000,64] = CRS[50000,128] @ linW[128,64] + linb
__global__ void final_kernel(const float* __restrict__ W,
                             const float* __restrict__ b,
                             float* __restrict__ out) {
  __shared__ float sW[128 * 64];
  __shared__ float sx[4][128];
  int tid = threadIdx.x;
  for (int i = tid; i < 128 * 64; i += 256) sW[i] = W[i];
  int n = tid & 63, rl = tid >> 6;
  int row = blockIdx.x * 4 + rl;
  for (int k = n; k < 128; k += 64)
    sx[rl][k] = (row < 50000) ? g_CRS[(size_t)row * HDIM + k] : 0.f;
  __syncthreads();
  float acc = 0.f;
#pragma unroll 16
  for (int k = 0; k < 128; ++k) acc += sx[rl][k] * sW[k * 64 + n];
  if (row < 50000) out[(size_t)row * 64 + n] = acc + b[n];
}

// ---------------- launch --------------------------------------------------------
extern "C" void kernel_launch(void* const* d_in, const int* in_sizes, int n_in,
                              void* d_out, int out_size) {
  (void)in_sizes; (void)n_in; (void)out_size;
  const float* X[10];
  for (int t = 0; t < 10; ++t) X[t] = (const float*)d_in[t];
  const int* EI[13];
  for (int i = 0; i < 13; ++i) EI[i] = (const int*)d_in[10 + i];
  const float* Wl   = (const float*)d_in[23];
  const float* bl   = (const float*)d_in[24];
  const float* Wr   = (const float*)d_in[25];
  const float* linW = (const float*)d_in[26];
  const float* linb = (const float*)d_in[27];
  float* out = (float*)d_out;

  void *pZBUF = 0, *pXBUF = 0, *pCRS = 0;
  cudaGetSymbolAddress(&pZBUF, g_ZBUF);
  cudaGetSymbolAddress(&pXBUF, g_XBUF);
  cudaGetSymbolAddress(&pCRS, g_CRS);
  float* XBUF = (float*)pXBUF;
  float* CRS = (float*)pCRS;

  cudaFuncSetAttribute(gemm_kernel, cudaFuncAttributeMaxDynamicSharedMemorySize, SM_BYTES);

  static const int TYPE_OFF[7] = {0, 50000, 52000, 132000, 142000, 144000, 294000};

  long long degOff[26];
  {
    long long cum = 0;
    for (int k = 0; k < 22; ++k) { int r = L1_RELS[k]; degOff[r] = cum; cum += NODE_N[REL[r].d]; }
  }

  ScatParams s1 = {};
  for (int k = 0; k < 22; ++k) {
    int r = L1_RELS[k];
    s1.ei[k] = EI[REL[r].ei];
    s1.xsrc[k] = X[REL[r].s];
    s1.aggOff[k] = degOff[r];
    s1.flip[k] = REL[r].flip;
  }
  ScatParams s2 = {};
  for (int k = 0; k < 6; ++k) {
    int r = L2_RELS[k];
    s2.ei[k] = EI[REL[r].ei];
    s2.xsrc[k] = XBUF + (size_t)TYPE_OFF[REL[r].s] * HDIM;
    s2.aggOff[k] = (long long)k * 50000;
    s2.flip[k] = REL[r].flip;
  }

  BPrepParams bp = {};
  int img = 0;

  GemmParams g1 = {};
  g1.nJobs = 7; g1.relu = 1;
  int cumblk = 0;
  for (int t = 0; t < 7; ++t) {
    g1.rowBlkStart[t] = cumblk;
    cumblk += (NODE_N[t] + 127) / 128;
    g1.nRows[t] = NODE_N[t];
    g1.xCur[t] = X[t];
    g1.outPtr[t] = XBUF + (size_t)TYPE_OFF[t] * HDIM;
    g1.bsumIdx[t] = t;
    int n = 0;
    g1.bimg[t][0] = img;
    for (int k = 0; k < 22; ++k) {
      int r = L1_RELS[k];
      if (REL[r].d == t) { bp.src[img][n] = Wr + (size_t)r * 16384; ++n; }
    }
    bp.nSrc[img] = n; ++img;
    n = 0;
    for (int k = 0; k < 22; ++k) {
      int r = L1_RELS[k];
      if (REL[r].d == t) {
        g1.bimg[t][1 + n] = img;
        bp.src[img][0] = Wl + (size_t)r * 16384; bp.nSrc[img] = 1; ++img;
        g1.wlRaw[t][n] = Wl + (size_t)r * 16384;
        g1.aggOff[t][n] = degOff[r];
        g1.degOff[t][n] = degOff[r];
        ++n;
      }
    }
    g1.nRel[t] = n;
  }
  g1.rowBlkStart[7] = cumblk;

  GemmParams g2 = {};
  g2.nJobs = 1; g2.relu = 1;
  int g2blocks = (NODE_N[0] + 127) / 128;
  g2.rowBlkStart[0] = 0; g2.rowBlkStart[1] = g2blocks;
  g2.nRows[0] = NODE_N[0];
  g2.xCur[0] = XBUF;
  g2.outPtr[0] = CRS;
  g2.bsumIdx[0] = 7;
  g2.nRel[0] = 6;
  g2.bimg[0][0] = img;
  for (int k = 0; k < 6; ++k) bp.src[img][k] = Wr + ((size_t)26 + L2_RELS[k]) * 16384;
  bp.nSrc[img] = 6; ++img;
  for (int k = 0; k < 6; ++k) {
    int r = L2_RELS[k];
    g2.bimg[0][1 + k] = img;
    bp.src[img][0] = Wl + ((size_t)26 + r) * 16384; bp.nSrc[img] = 1; ++img;
    g2.wlRaw[0][k] = Wl + ((size_t)26 + r) * 16384;
    g2.aggOff[0][k] = (long long)k * 50000;
    g2.degOff[0][k] = degOff[r];
  }
  int nImgs = img;   // 36

  for (int t = 0; t < 7; ++t) {
    int n = 0;
    for (int k = 0; k < 22; ++k) {
      int r = L1_RELS[k];
      if (REL[r].d == t) bp.bsrc[t][n++] = bl + (size_t)r * 128;
    }
    bp.bN[t] = n;
  }
  for (int k = 0; k < 6; ++k) bp.bsrc[7][k] = bl + ((size_t)26 + L2_RELS[k]) * 128;
  bp.bN[7] = 6;

  // ---- execution ----
  cudaMemsetAsync(pZBUF, 0, ((size_t)L1_ROWS * HDIM + L1_ROWS) * sizeof(float), 0);
  deg_kernel<<<dim3((EDGES + 255) / 256, 22), 256>>>(s1);
  bprep_kernel<<<dim3(nImgs + 1, 4), 256>>>(bp);
  scatter_kernel<<<dim3(9375, 22), 256>>>(s1);
  gemm_kernel<<<148, 512, SM_BYTES>>>(g1);

  cudaMemsetAsync(pZBUF, 0, (size_t)300000 * HDIM * sizeof(float), 0);
  scatter_kernel<<<dim3(9375, 6), 256>>>(s2);
  gemm_kernel<<<148, 512, SM_BYTES>>>(g2);
  final_kernel<<<(50000 + 3) / 4, 256>>>(linW, linb, out);
}